// round 15
// baseline (speedup 1.0000x reference)
#include <cuda_runtime.h>
#include <cuda_bf16.h>
#include <cstdint>

#define NIMG 8
#define NA   3
#define HH   100
#define WW   100
#define NHW  10000
#define NANC 30000          // H*W*A
#define PRE  2000
#define PREP 2048           // padded to pow2 for bitonic sort
#define POST 1000
#define NWRD 32             // ceil(2000/64) mask words per row
#define NTILE 32            // 64-row tiles
#define IMGW 1600.0f
#define BBOX_CLIP 4.135166556742356f   // log(1000/16)
#define NMS_THR 0.7f

typedef unsigned long long u64;
typedef unsigned int       u32;

// ---------------- device-global scratch (no runtime allocation) ----------------
__device__ float4             g_boxes[NIMG][PRE];
__device__ float              g_scores[NIMG][PRE];
__device__ unsigned char      g_valid[NIMG][PREP];         // padded: lanes read 64B each
__device__ u64                g_mask[NIMG][PRE][NWRD];     // ~4.1 MB

// monotonic map: float total order -> u32 unsigned order (no NaN in inputs)
__device__ __forceinline__ u32 fmap(float f) {
    u32 b = __float_as_uint(f);
    return (b & 0x80000000u) ? ~b : (b | 0x80000000u);
}
__device__ __forceinline__ float funmap(u32 k) {
    u32 b = (k & 0x80000000u) ? (k & 0x7FFFFFFFu) : ~k;
    return __uint_as_float(b);
}

// =============================================================================
// Kernel A: key-map -> radix-select threshold -> compact -> bitonic sort ->
//           sigmoid+decode/clip (survivors only).  One block (1024 thr)/image.
// =============================================================================
__global__ __launch_bounds__(1024)
void topk_decode_kernel(const float* __restrict__ obj_all,
                        const float* __restrict__ reg_all,
                        const float* __restrict__ anc_all)
{
    extern __shared__ unsigned char smem_raw[];
    u32* s_sb   = (u32*)smem_raw;                  // 30000 u32
    u64* s_keys = (u64*)(smem_raw + 120000);       // 2048 u64

    __shared__ u32 s_hist[256];
    __shared__ u32 s_cnt;
    __shared__ u32 s_prefix;
    __shared__ int s_K;

    const int img = blockIdx.x;
    const int tid = threadIdx.x;

    // ---- phase 1: monotonic key + transpose into smem (sigmoid deferred;
    //      stride-3 word smem store is conflict-free: gcd(3,32)=1) ----
    {
        const float* obj = obj_all + (size_t)img * NANC;   // layout a*NHW + hw
        for (int i = tid; i < NANC; i += 1024) {
            int a  = i / NHW;
            int hw = i - a * NHW;
            s_sb[hw * NA + a] = fmap(obj[i]);
        }
    }
    if (tid == 0) { s_prefix = 0; s_K = PRE; }
    __syncthreads();

    // ---- phase 2: 4-pass MSB radix select for the PRE-th largest key ----
    // Pass 0: all 30000 keys active and heavily clustered in few bins ->
    // warp-aggregated atomics (match_any + leader popc add) to break the
    // 32-lane same-address ATOMS serialization. Passes 1-3: few active
    // lanes, plain atomics are cheaper than the collective machinery.
    u32 pmask = 0;
    for (int pass = 0; pass < 4; ++pass) {
        int shift = 24 - 8 * pass;
        if (tid < 256) s_hist[tid] = 0;
        __syncthreads();
        u32 prefix = s_prefix;
        if (pass == 0) {
            // padded uniform trip count so warp collectives are legal
            for (int base = 0; base < 30720; base += 1024) {
                int i = base + tid;
                bool act = (i < NANC);
                u32 v = act ? s_sb[i] : 0u;
                u32 bin = (v >> shift) & 255u;
                u32 amask = __ballot_sync(0xFFFFFFFFu, act);
                if (act) {
                    u32 peers = __match_any_sync(amask, bin);
                    int leader = __ffs((int)peers) - 1;
                    if ((tid & 31) == leader)
                        atomicAdd(&s_hist[bin], (u32)__popc(peers));
                }
            }
        } else {
            for (int i = tid; i < NANC; i += 1024) {
                u32 v = s_sb[i];
                if ((v & pmask) == prefix)
                    atomicAdd(&s_hist[(v >> shift) & 255u], 1u);
            }
        }
        __syncthreads();
        // warp 0: shfl-based suffix scan over 256 bins (no barrier loop)
        if (tid < 32) {
            const int lane = tid;
            u32 h[8];
            u32 chunk = 0;
            #pragma unroll
            for (int j = 0; j < 8; ++j) { h[j] = s_hist[lane * 8 + j]; chunk += h[j]; }
            u32 s_incl = chunk;
            #pragma unroll
            for (int off = 1; off < 32; off <<= 1) {
                u32 t = __shfl_down_sync(0xFFFFFFFFu, s_incl, off);
                if (lane + off < 32) s_incl += t;
            }
            const u32 s_excl = s_incl - chunk;  // sum of chunks with lane' > lane
            const int Kc = s_K;
            u32 suf = s_excl;                   // S[bin 8L+8]
            #pragma unroll
            for (int j = 7; j >= 0; --j) {
                u32 nxt = suf;                  // S[bin+1]
                suf += h[j];                    // S[bin]
                if ((int)suf >= Kc && (int)nxt < Kc) {
                    s_K = Kc - (int)nxt;
                    s_prefix = prefix | ((u32)(lane * 8 + j) << shift);
                }
            }
        }
        pmask |= (0xFFu << shift);
        __syncthreads();
    }
    const u32 T = s_prefix;   // exact bits of the PRE-th largest key

    // ---- phase 3: compact candidates >= T ----
    if (tid == 0) s_cnt = 0;
    __syncthreads();
    for (int i = tid; i < NANC; i += 1024) {
        u32 v = s_sb[i];
        if (v >= T) {
            u32 pos = atomicAdd(&s_cnt, 1u);
            if (pos < PREP)
                s_keys[pos] = ((u64)v << 32) | (u64)(~(u32)i);
        }
    }
    __syncthreads();
    u32 n = s_cnt; if (n > PREP) n = PREP;
    for (int i = tid; i < PREP; i += 1024)
        if (i >= (int)n) s_keys[i] = 0ULL;
    __syncthreads();

    // ---- phase 4: bitonic sort (descending) of 2048 keys ----
    for (int k = 2; k <= PREP; k <<= 1) {
        for (int j = k >> 1; j > 0; j >>= 1) {
            for (int i = tid; i < PREP; i += 1024) {
                int l = i ^ j;
                if (l > i) {
                    u64 a = s_keys[i];
                    u64 b = s_keys[l];
                    bool up = ((i & k) == 0);
                    if ((a < b) == up) { s_keys[i] = b; s_keys[l] = a; }
                }
            }
            __syncthreads();
        }
    }

    // ---- phase 5: sigmoid (survivors only) + decode / clip / validity ----
    const float* reg = reg_all + (size_t)img * NA * 4 * NHW;
    const float4* anc = (const float4*)anc_all + (size_t)img * NANC;
    for (int j = tid; j < PRE; j += 1024) {
        u64 key = s_keys[j];
        u32 idx = ~(u32)(key & 0xFFFFFFFFull);
        float o = funmap((u32)(key >> 32));
        float score = 1.0f / (1.0f + expf(-o));

        int hw = idx / NA;
        int a  = idx - hw * NA;
        const float* rb = reg + (a * 4) * NHW + hw;
        float dx = rb[0];
        float dy = rb[NHW];
        float dw = rb[2 * NHW];
        float dh = rb[3 * NHW];
        dw = fminf(dw, BBOX_CLIP);
        dh = fminf(dh, BBOX_CLIP);

        float4 A4 = anc[idx];
        float w  = A4.z - A4.x + 1.0f;
        float h  = A4.w - A4.y + 1.0f;
        float cx = A4.x + 0.5f * w;
        float cy = A4.y + 0.5f * h;

        float pcx = dx * w + cx;
        float pcy = dy * h + cy;
        float pw  = expf(dw) * w;
        float ph  = expf(dh) * h;

        float x1 = pcx - 0.5f * pw;
        float y1 = pcy - 0.5f * ph;
        float x2 = pcx + 0.5f * pw - 1.0f;
        float y2 = pcy + 0.5f * ph - 1.0f;

        x1 = fminf(fmaxf(x1, 0.0f), IMGW - 1.0f);
        x2 = fminf(fmaxf(x2, 0.0f), IMGW - 1.0f);
        y1 = fminf(fmaxf(y1, 0.0f), IMGW - 1.0f);
        y2 = fminf(fmaxf(y2, 0.0f), IMGW - 1.0f);

        float ws = x2 - x1 + 1.0f;
        float hs = y2 - y1 + 1.0f;
        float xc = x1 + ws * 0.5f;
        float yc = y1 + hs * 0.5f;
        unsigned char v = (ws >= 0.0f) & (hs >= 0.0f) & (xc < IMGW) & (yc < IMGW);

        g_boxes[img][j]  = make_float4(x1, y1, x2, y2);
        g_scores[img][j] = score;
        g_valid[img][j]  = v;
    }
    // zero the pad bytes so kernel C's packed reads are well-defined
    for (int j = PRE + tid; j < PREP; j += 1024) g_valid[img][j] = 0;
}

// =============================================================================
// Kernel B: NMS suppression bitmask. grid (colBlk=32, rowQuad=8, img=8), 256 thr
// =============================================================================
__global__ __launch_bounds__(256)
void nms_mask_kernel()
{
    const int img    = blockIdx.z;
    const int colBlk = blockIdx.x;
    const int row    = blockIdx.y * 256 + threadIdx.x;

    __shared__ float4 s_col[64];
    const int colBase = colBlk * 64;
    if (threadIdx.x < 64) {
        int c = colBase + threadIdx.x;
        if (c < PRE) s_col[threadIdx.x] = g_boxes[img][c];
    }
    __syncthreads();

    if (row >= PRE) return;
    if (colBlk < (row >> 6)) {             // tile entirely below diagonal
        g_mask[img][row][colBlk] = 0ULL;
        return;
    }

    float4 rb = g_boxes[img][row];
    float rArea = (rb.z - rb.x + 1.0f) * (rb.w - rb.y + 1.0f);
    u64 bits = 0ULL;
    int nCols = PRE - colBase; if (nCols > 64) nCols = 64;

    for (int jj = 0; jj < nCols; ++jj) {
        int col = colBase + jj;
        if (col <= row) continue;
        float4 cb = s_col[jj];
        float xx1 = fmaxf(rb.x, cb.x);
        float yy1 = fmaxf(rb.y, cb.y);
        float xx2 = fminf(rb.z, cb.z);
        float yy2 = fminf(rb.w, cb.w);
        float iw = fmaxf(xx2 - xx1 + 1.0f, 0.0f);
        float ih = fmaxf(yy2 - yy1 + 1.0f, 0.0f);
        float inter = iw * ih;
        float cArea = (cb.z - cb.x + 1.0f) * (cb.w - cb.y + 1.0f);
        float iou = inter / (rArea + cArea - inter);
        if (iou > NMS_THR) bits |= (1ULL << jj);
    }
    g_mask[img][row][colBlk] = bits;
}

// =============================================================================
// Kernel C: greedy scan via double-buffered SMEM tiles. 256 threads/image.
//   warps 1..7 : copy tile t+1 (64 rows x 32 words = 16KB) gmem -> smem
//   warp 0     : scan tile t; serial chain on 32-BIT halves of cur (the
//                tested bit's half is compile-time known per group of 8),
//                keeps recorded in a register bitmask; popc+__fns emit.
//   1 shfl + 1 __syncthreads per tile; uniform early exit at tile boundaries.
// Output layout: boxes[8*1000*4] | scores[8*1000] | valid[8*1000]  (float32)
// =============================================================================
__global__ __launch_bounds__(256)
void nms_reduce_kernel(float* __restrict__ out)
{
    const int img  = blockIdx.x;
    const int tid  = threadIdx.x;
    const int lane = tid & 31;
    const int wid  = tid >> 5;

    __shared__ u64 s_tile[2][64][NWRD];      // 32 KB double-buffered mask tile
    __shared__ int s_kept[POST];
    __shared__ int s_kdone;

    float* outB = out;                       // (8,1000,4)
    float* outS = out + NIMG * POST * 4;     // (8,1000)
    float* outV = out + NIMG * POST * 5;     // (8,1000)

    // zero outputs (all threads; fast)
    for (int i = tid; i < POST * 4; i += 256) outB[img * POST * 4 + i] = 0.0f;
    for (int i = tid; i < POST;     i += 256) {
        outS[img * POST + i] = 0.0f;
        outV[img * POST + i] = 0.0f;
    }
    if (tid == 0) s_kdone = 0;

    // preload tile 0 (all threads)
    {
        const u64* src = &g_mask[img][0][0];
        for (int i = tid; i < 64 * NWRD; i += 256)
            s_tile[0][0][i] = src[i];        // rows 0..63 fully in range
    }

    // scanner warp state: removed-word per lane, seeded by ~valid
    u64 rw = 0ULL;
    if (wid == 0) {
        const u64* vp = (const u64*)g_valid[img];
        u64 bits = 0ULL;
        #pragma unroll
        for (int q = 0; q < 8; ++q) {
            u64 v8 = vp[lane * 8 + q];
            #pragma unroll
            for (int b = 0; b < 8; ++b)
                if ((v8 >> (8 * b)) & 0xFFull) bits |= 1ULL << (q * 8 + b);
        }
        rw = ~bits;
    }
    __syncthreads();

    int k = 0;
    for (int t = 0; t < NTILE; ++t) {
        if (wid >= 1) {
            // loaders: fill the other buffer with tile t+1 (zero-fill OOB rows)
            const int t1 = t + 1;
            if (t1 < NTILE) {
                const int r0 = t1 * 64;
                const int nval = (PRE - r0 < 64 ? PRE - r0 : 64) * NWRD;
                const u64* src = &g_mask[img][r0][0];
                u64* dst = &s_tile[t1 & 1][0][0];
                for (int i = tid - 32; i < 64 * NWRD; i += 224)
                    dst[i] = (i < nval) ? src[i] : 0ULL;
            }
        } else {
            // scanner: walk 64 candidates of tile t, record keeps in a bitmask
            const u64 (*tp)[NWRD] = s_tile[t & 1];
            u64 cur0 = __shfl_sync(0xFFFFFFFFu, rw, t);  // word t state
            u32 clo = (u32)cur0, chi = (u32)(cur0 >> 32);
            u64 keptw = 0ULL;
            #pragma unroll 1
            for (int g = 0; g < 8; ++g) {                // 8 groups of 8
                const int j0 = g * 8;
                // batched LDS (off the serial chain)
                u64 m[8], ms[8];
                #pragma unroll
                for (int j = 0; j < 8; ++j) {
                    m[j]  = tp[j0 + j][lane];
                    ms[j] = tp[j0 + j][t];               // uniform broadcast
                }
                // serial chain on the compile-time-known 32-bit half of cur
                #pragma unroll
                for (int j = 0; j < 8; ++j) {
                    const int  bi   = j0 + j;
                    const u32  bit32 = 1u << (bi & 31);
                    const bool kept = (j0 < 32) ? ((clo & bit32) == 0u)
                                                : ((chi & bit32) == 0u);
                    const u32 mslo = (u32)ms[j], mshi = (u32)(ms[j] >> 32);
                    clo   |= kept ? mslo : 0u;
                    chi   |= kept ? mshi : 0u;
                    rw    |= kept ? m[j] : 0ULL;         // off chain
                    keptw |= kept ? (1ULL << bi) : 0ULL; // off chain
                }
            }
            // per-tile emit: lanes extract kept indices from the bitmask
            const u32 lo = (u32)keptw, hi = (u32)(keptw >> 32);
            const int nlo = __popc(lo);
            const int ncnt = nlo + __popc(hi);
            #pragma unroll
            for (int r = 0; r < 2; ++r) {
                const int idx = lane + r * 32;
                if (idx < ncnt && k + idx < POST) {
                    int pos = (idx < nlo) ? __fns(lo, 0, idx + 1)
                                          : 32 + __fns(hi, 0, idx - nlo + 1);
                    s_kept[k + idx] = t * 64 + pos;
                }
            }
            k += ncnt;
            if (lane == 0) s_kdone = k;
        }
        __syncthreads();
        if (s_kdone >= POST) break;          // uniform across the block
    }

    const int nk = (s_kdone < POST) ? s_kdone : POST;
    for (int j = tid; j < nk; j += 256) {
        int i = s_kept[j];
        float4 b = g_boxes[img][i];
        ((float4*)outB)[img * POST + j] = b;
        outS[img * POST + j] = g_scores[img][i];
        outV[img * POST + j] = 1.0f;
    }
}

// =============================================================================
extern "C" void kernel_launch(void* const* d_in, const int* in_sizes, int n_in,
                              void* d_out, int out_size)
{
    const float* obj = (const float*)d_in[0];   // (8,3,100,100)
    const float* reg = (const float*)d_in[1];   // (8,12,100,100)
    const float* anc = (const float*)d_in[2];   // (8,30000,4)
    float* out = (float*)d_out;
    (void)in_sizes; (void)n_in; (void)out_size;

    const int smemA = 120000 + PREP * 8;        // 136384 bytes dynamic
    cudaFuncSetAttribute(topk_decode_kernel,
                         cudaFuncAttributeMaxDynamicSharedMemorySize, smemA);

    topk_decode_kernel<<<NIMG, 1024, smemA>>>(obj, reg, anc);
    dim3 gB(NWRD, 8, NIMG);
    nms_mask_kernel<<<gB, 256>>>();
    nms_reduce_kernel<<<NIMG, 256>>>(out);
}

// round 16
// speedup vs baseline: 1.1028x; 1.1028x over previous
#include <cuda_runtime.h>
#include <cuda_bf16.h>
#include <cstdint>

#define NIMG 8
#define NA   3
#define HH   100
#define WW   100
#define NHW  10000
#define NANC 30000          // H*W*A
#define PRE  2000
#define PREP 2048           // padded to pow2 for bitonic sort
#define POST 1000
#define NWRD 32             // ceil(2000/64) mask words per row
#define NTILE 32            // 64-row tiles
#define IMGW 1600.0f
#define BBOX_CLIP 4.135166556742356f   // log(1000/16)
#define NMS_THR 0.7f

typedef unsigned long long u64;
typedef unsigned int       u32;

// ---------------- device-global scratch (no runtime allocation) ----------------
__device__ float4             g_boxes[NIMG][PRE];
__device__ float              g_scores[NIMG][PRE];
__device__ unsigned char      g_valid[NIMG][PREP];         // padded: lanes read 64B each
__device__ u64                g_mask[NIMG][PRE][NWRD];     // ~4.1 MB

// monotonic map: float total order -> u32 unsigned order (no NaN in inputs)
__device__ __forceinline__ u32 fmap(float f) {
    u32 b = __float_as_uint(f);
    return (b & 0x80000000u) ? ~b : (b | 0x80000000u);
}
__device__ __forceinline__ float funmap(u32 k) {
    u32 b = (k & 0x80000000u) ? (k & 0x7FFFFFFFu) : ~k;
    return __uint_as_float(b);
}

__device__ __forceinline__ u64 umax64(u64 a, u64 b) { return a > b ? a : b; }
__device__ __forceinline__ u64 umin64(u64 a, u64 b) { return a < b ? a : b; }

// =============================================================================
// Kernel A: key-map -> radix-select threshold -> compact -> hybrid bitonic ->
//           sigmoid+decode/clip (survivors only).  One block (1024 thr)/image.
// =============================================================================
__global__ __launch_bounds__(1024)
void topk_decode_kernel(const float* __restrict__ obj_all,
                        const float* __restrict__ reg_all,
                        const float* __restrict__ anc_all)
{
    extern __shared__ unsigned char smem_raw[];
    u32* s_sb   = (u32*)smem_raw;                  // 30000 u32
    u64* s_keys = (u64*)(smem_raw + 120000);       // 2048 u64

    __shared__ u32 s_hist[256];
    __shared__ u32 s_cnt;
    __shared__ u32 s_prefix;
    __shared__ int s_K;

    const int img = blockIdx.x;
    const int tid = threadIdx.x;

    // ---- phase 1: monotonic key + transpose into smem (sigmoid deferred;
    //      stride-3 word smem store is conflict-free: gcd(3,32)=1) ----
    {
        const float* obj = obj_all + (size_t)img * NANC;   // layout a*NHW + hw
        for (int i = tid; i < NANC; i += 1024) {
            int a  = i / NHW;
            int hw = i - a * NHW;
            s_sb[hw * NA + a] = fmap(obj[i]);
        }
    }
    if (tid == 0) { s_prefix = 0; s_K = PRE; }
    __syncthreads();

    // ---- phase 2: 4-pass MSB radix select for the PRE-th largest key ----
    u32 pmask = 0;
    for (int pass = 0; pass < 4; ++pass) {
        int shift = 24 - 8 * pass;
        if (tid < 256) s_hist[tid] = 0;
        __syncthreads();
        u32 prefix = s_prefix;
        for (int i = tid; i < NANC; i += 1024) {
            u32 v = s_sb[i];
            if ((v & pmask) == prefix)
                atomicAdd(&s_hist[(v >> shift) & 255u], 1u);
        }
        __syncthreads();
        // warp 0: shfl-based suffix scan over 256 bins (no barrier loop)
        if (tid < 32) {
            const int lane = tid;
            u32 h[8];
            u32 chunk = 0;
            #pragma unroll
            for (int j = 0; j < 8; ++j) { h[j] = s_hist[lane * 8 + j]; chunk += h[j]; }
            u32 s_incl = chunk;
            #pragma unroll
            for (int off = 1; off < 32; off <<= 1) {
                u32 t = __shfl_down_sync(0xFFFFFFFFu, s_incl, off);
                if (lane + off < 32) s_incl += t;
            }
            const u32 s_excl = s_incl - chunk;  // sum of chunks with lane' > lane
            const int Kc = s_K;
            u32 suf = s_excl;                   // S[bin 8L+8]
            #pragma unroll
            for (int j = 7; j >= 0; --j) {
                u32 nxt = suf;                  // S[bin+1]
                suf += h[j];                    // S[bin]
                if ((int)suf >= Kc && (int)nxt < Kc) {
                    s_K = Kc - (int)nxt;
                    s_prefix = prefix | ((u32)(lane * 8 + j) << shift);
                }
            }
        }
        pmask |= (0xFFu << shift);
        __syncthreads();
    }
    const u32 T = s_prefix;   // exact bits of the PRE-th largest key

    // ---- phase 3: compact candidates >= T ----
    if (tid == 0) s_cnt = 0;
    __syncthreads();
    for (int i = tid; i < NANC; i += 1024) {
        u32 v = s_sb[i];
        if (v >= T) {
            u32 pos = atomicAdd(&s_cnt, 1u);
            if (pos < PREP)
                s_keys[pos] = ((u64)v << 32) | (u64)(~(u32)i);
        }
    }
    __syncthreads();
    u32 n = s_cnt; if (n > PREP) n = PREP;
    for (int i = tid; i < PREP; i += 1024)
        if (i >= (int)n) s_keys[i] = 0ULL;
    __syncthreads();

    // ---- phase 4: hybrid bitonic sort (descending) of 2048 keys.
    //      Thread t holds elements e0=2t, e1=2t+1 in REGISTERS.
    //      j==1   : in-thread compare            (no barrier)
    //      j<=32  : shfl_xor exchange, same warp (no barrier)
    //      j>=64  : smem exchange                (2 barriers; 15 substeps)
    {
        const int e0 = 2 * tid;
        u64 a = s_keys[e0];
        u64 b = s_keys[e0 + 1];
        for (int k = 2; k <= PREP; k <<= 1) {
            const bool up = ((e0 & k) == 0);           // same for e0 and e1 (k>=2)
            for (int j = k >> 1; j > 0; j >>= 1) {
                if (j == 1) {
                    // pair (e0, e1): lower index = e0
                    if ((a < b) == up) { u64 t = a; a = b; b = t; }
                } else if (j <= 32) {
                    const int lx = j >> 1;             // partner lane xor
                    u64 pa = __shfl_xor_sync(0xFFFFFFFFu, a, lx);
                    u64 pb = __shfl_xor_sync(0xFFFFFFFFu, b, lx);
                    const bool lower = ((e0 & j) == 0); // same for e0,e1 (j>=2)
                    a = (lower == up) ? umax64(a, pa) : umin64(a, pa);
                    b = (lower == up) ? umax64(b, pb) : umin64(b, pb);
                } else {
                    s_keys[e0]     = a;
                    s_keys[e0 + 1] = b;
                    __syncthreads();
                    u64 pa = s_keys[e0 ^ j];
                    u64 pb = s_keys[(e0 + 1) ^ j];
                    const bool lower = ((e0 & j) == 0);
                    a = (lower == up) ? umax64(a, pa) : umin64(a, pa);
                    b = (lower == up) ? umax64(b, pb) : umin64(b, pb);
                    __syncthreads();                   // reads done before next write
                }
            }
        }
        s_keys[e0]     = a;
        s_keys[e0 + 1] = b;
        __syncthreads();
    }

    // ---- phase 5: sigmoid (survivors only) + decode / clip / validity ----
    const float* reg = reg_all + (size_t)img * NA * 4 * NHW;
    const float4* anc = (const float4*)anc_all + (size_t)img * NANC;
    for (int j = tid; j < PRE; j += 1024) {
        u64 key = s_keys[j];
        u32 idx = ~(u32)(key & 0xFFFFFFFFull);
        float o = funmap((u32)(key >> 32));
        float score = 1.0f / (1.0f + expf(-o));

        int hw = idx / NA;
        int a  = idx - hw * NA;
        const float* rb = reg + (a * 4) * NHW + hw;
        float dx = rb[0];
        float dy = rb[NHW];
        float dw = rb[2 * NHW];
        float dh = rb[3 * NHW];
        dw = fminf(dw, BBOX_CLIP);
        dh = fminf(dh, BBOX_CLIP);

        float4 A4 = anc[idx];
        float w  = A4.z - A4.x + 1.0f;
        float h  = A4.w - A4.y + 1.0f;
        float cx = A4.x + 0.5f * w;
        float cy = A4.y + 0.5f * h;

        float pcx = dx * w + cx;
        float pcy = dy * h + cy;
        float pw  = expf(dw) * w;
        float ph  = expf(dh) * h;

        float x1 = pcx - 0.5f * pw;
        float y1 = pcy - 0.5f * ph;
        float x2 = pcx + 0.5f * pw - 1.0f;
        float y2 = pcy + 0.5f * ph - 1.0f;

        x1 = fminf(fmaxf(x1, 0.0f), IMGW - 1.0f);
        x2 = fminf(fmaxf(x2, 0.0f), IMGW - 1.0f);
        y1 = fminf(fmaxf(y1, 0.0f), IMGW - 1.0f);
        y2 = fminf(fmaxf(y2, 0.0f), IMGW - 1.0f);

        float ws = x2 - x1 + 1.0f;
        float hs = y2 - y1 + 1.0f;
        float xc = x1 + ws * 0.5f;
        float yc = y1 + hs * 0.5f;
        unsigned char v = (ws >= 0.0f) & (hs >= 0.0f) & (xc < IMGW) & (yc < IMGW);

        g_boxes[img][j]  = make_float4(x1, y1, x2, y2);
        g_scores[img][j] = score;
        g_valid[img][j]  = v;
    }
    // zero the pad bytes so kernel C's packed reads are well-defined
    for (int j = PRE + tid; j < PREP; j += 1024) g_valid[img][j] = 0;
}

// =============================================================================
// Kernel B: NMS suppression bitmask. grid (colBlk=32, rowQuad=8, img=8), 256 thr
// =============================================================================
__global__ __launch_bounds__(256)
void nms_mask_kernel()
{
    const int img    = blockIdx.z;
    const int colBlk = blockIdx.x;
    const int row    = blockIdx.y * 256 + threadIdx.x;

    __shared__ float4 s_col[64];
    const int colBase = colBlk * 64;
    if (threadIdx.x < 64) {
        int c = colBase + threadIdx.x;
        if (c < PRE) s_col[threadIdx.x] = g_boxes[img][c];
    }
    __syncthreads();

    if (row >= PRE) return;
    if (colBlk < (row >> 6)) {             // tile entirely below diagonal
        g_mask[img][row][colBlk] = 0ULL;
        return;
    }

    float4 rb = g_boxes[img][row];
    float rArea = (rb.z - rb.x + 1.0f) * (rb.w - rb.y + 1.0f);
    u64 bits = 0ULL;
    int nCols = PRE - colBase; if (nCols > 64) nCols = 64;

    for (int jj = 0; jj < nCols; ++jj) {
        int col = colBase + jj;
        if (col <= row) continue;
        float4 cb = s_col[jj];
        float xx1 = fmaxf(rb.x, cb.x);
        float yy1 = fmaxf(rb.y, cb.y);
        float xx2 = fminf(rb.z, cb.z);
        float yy2 = fminf(rb.w, cb.w);
        float iw = fmaxf(xx2 - xx1 + 1.0f, 0.0f);
        float ih = fmaxf(yy2 - yy1 + 1.0f, 0.0f);
        float inter = iw * ih;
        float cArea = (cb.z - cb.x + 1.0f) * (cb.w - cb.y + 1.0f);
        float iou = inter / (rArea + cArea - inter);
        if (iou > NMS_THR) bits |= (1ULL << jj);
    }
    g_mask[img][row][colBlk] = bits;
}

// =============================================================================
// Kernel C: greedy scan via double-buffered SMEM tiles. 256 threads/image.
//   (exact R14 state — known 127.5us total)
// Output layout: boxes[8*1000*4] | scores[8*1000] | valid[8*1000]  (float32)
// =============================================================================
__global__ __launch_bounds__(256)
void nms_reduce_kernel(float* __restrict__ out)
{
    const int img  = blockIdx.x;
    const int tid  = threadIdx.x;
    const int lane = tid & 31;
    const int wid  = tid >> 5;

    __shared__ u64 s_tile[2][64][NWRD];      // 32 KB double-buffered mask tile
    __shared__ int s_kept[POST];
    __shared__ int s_kdone;

    float* outB = out;                       // (8,1000,4)
    float* outS = out + NIMG * POST * 4;     // (8,1000)
    float* outV = out + NIMG * POST * 5;     // (8,1000)

    // zero outputs (all threads; fast)
    for (int i = tid; i < POST * 4; i += 256) outB[img * POST * 4 + i] = 0.0f;
    for (int i = tid; i < POST;     i += 256) {
        outS[img * POST + i] = 0.0f;
        outV[img * POST + i] = 0.0f;
    }
    if (tid == 0) s_kdone = 0;

    // preload tile 0 (all threads)
    {
        const u64* src = &g_mask[img][0][0];
        for (int i = tid; i < 64 * NWRD; i += 256)
            s_tile[0][0][i] = src[i];        // rows 0..63 fully in range
    }

    // scanner warp state: removed-word per lane, seeded by ~valid
    u64 rw = 0ULL;
    if (wid == 0) {
        const u64* vp = (const u64*)g_valid[img];
        u64 bits = 0ULL;
        #pragma unroll
        for (int q = 0; q < 8; ++q) {
            u64 v8 = vp[lane * 8 + q];
            #pragma unroll
            for (int b = 0; b < 8; ++b)
                if ((v8 >> (8 * b)) & 0xFFull) bits |= 1ULL << (q * 8 + b);
        }
        rw = ~bits;
    }
    __syncthreads();

    int k = 0;
    for (int t = 0; t < NTILE; ++t) {
        if (wid >= 1) {
            // loaders: fill the other buffer with tile t+1 (zero-fill OOB rows)
            const int t1 = t + 1;
            if (t1 < NTILE) {
                const int r0 = t1 * 64;
                const int nval = (PRE - r0 < 64 ? PRE - r0 : 64) * NWRD;
                const u64* src = &g_mask[img][r0][0];
                u64* dst = &s_tile[t1 & 1][0][0];
                for (int i = tid - 32; i < 64 * NWRD; i += 224)
                    dst[i] = (i < nval) ? src[i] : 0ULL;
            }
        } else {
            // scanner: walk 64 candidates of tile t, record keeps in a bitmask
            const u64 (*tp)[NWRD] = s_tile[t & 1];
            u64 cur = __shfl_sync(0xFFFFFFFFu, rw, t);   // word t state
            u64 keptw = 0ULL;
            #pragma unroll 1
            for (int g = 0; g < 8; ++g) {                // 8 groups of 8
                const int j0 = g * 8;
                // batched LDS (off the serial chain)
                u64 m[8], ms[8];
                #pragma unroll
                for (int j = 0; j < 8; ++j) {
                    m[j]  = tp[j0 + j][lane];
                    ms[j] = tp[j0 + j][t];               // uniform broadcast
                }
                // pure-ALU serial chain, zero stores
                #pragma unroll
                for (int j = 0; j < 8; ++j) {
                    const u64 bitj = 1ULL << (j0 + j);
                    const bool kept = (cur & bitj) == 0ULL;
                    cur   |= kept ? ms[j] : 0ULL;
                    rw    |= kept ? m[j]  : 0ULL;
                    keptw |= kept ? bitj  : 0ULL;
                }
            }
            // per-tile emit: lanes extract kept indices from the bitmask
            const u32 lo = (u32)keptw, hi = (u32)(keptw >> 32);
            const int nlo = __popc(lo);
            const int ncnt = nlo + __popc(hi);
            #pragma unroll
            for (int r = 0; r < 2; ++r) {
                const int idx = lane + r * 32;
                if (idx < ncnt && k + idx < POST) {
                    int pos = (idx < nlo) ? __fns(lo, 0, idx + 1)
                                          : 32 + __fns(hi, 0, idx - nlo + 1);
                    s_kept[k + idx] = t * 64 + pos;
                }
            }
            k += ncnt;
            if (lane == 0) s_kdone = k;
        }
        __syncthreads();
        if (s_kdone >= POST) break;          // uniform across the block
    }

    const int nk = (s_kdone < POST) ? s_kdone : POST;
    for (int j = tid; j < nk; j += 256) {
        int i = s_kept[j];
        float4 b = g_boxes[img][i];
        ((float4*)outB)[img * POST + j] = b;
        outS[img * POST + j] = g_scores[img][i];
        outV[img * POST + j] = 1.0f;
    }
}

// =============================================================================
extern "C" void kernel_launch(void* const* d_in, const int* in_sizes, int n_in,
                              void* d_out, int out_size)
{
    const float* obj = (const float*)d_in[0];   // (8,3,100,100)
    const float* reg = (const float*)d_in[1];   // (8,12,100,100)
    const float* anc = (const float*)d_in[2];   // (8,30000,4)
    float* out = (float*)d_out;
    (void)in_sizes; (void)n_in; (void)out_size;

    const int smemA = 120000 + PREP * 8;        // 136384 bytes dynamic
    cudaFuncSetAttribute(topk_decode_kernel,
                         cudaFuncAttributeMaxDynamicSharedMemorySize, smemA);

    topk_decode_kernel<<<NIMG, 1024, smemA>>>(obj, reg, anc);
    dim3 gB(NWRD, 8, NIMG);
    nms_mask_kernel<<<gB, 256>>>();
    nms_reduce_kernel<<<NIMG, 256>>>(out);
}

// round 17
// speedup vs baseline: 1.1623x; 1.0539x over previous
#include <cuda_runtime.h>
#include <cuda_bf16.h>
#include <cstdint>

#define NIMG 8
#define NA   3
#define HH   100
#define WW   100
#define NHW  10000
#define NANC 30000          // H*W*A
#define PRE  2000
#define PREP 2048           // padded to pow2 for bitonic sort
#define POST 1000
#define NWRD 32             // ceil(2000/64) mask words per row
#define NTILE 32            // 64-row tiles
#define IMGW 1600.0f
#define BBOX_CLIP 4.135166556742356f   // log(1000/16)
#define NMS_THR 0.7f

typedef unsigned long long u64;
typedef unsigned int       u32;

// ---------------- device-global scratch (no runtime allocation) ----------------
__device__ float4             g_boxes[NIMG][PRE];
__device__ float              g_scores[NIMG][PRE];
__device__ unsigned char      g_valid[NIMG][PREP];         // padded: lanes read 64B each
__device__ u64                g_mask[NIMG][PRE][NWRD];     // ~4.1 MB

// monotonic map: float total order -> u32 unsigned order (no NaN in inputs)
__device__ __forceinline__ u32 fmap(float f) {
    u32 b = __float_as_uint(f);
    return (b & 0x80000000u) ? ~b : (b | 0x80000000u);
}
__device__ __forceinline__ float funmap(u32 k) {
    u32 b = (k & 0x80000000u) ? (k & 0x7FFFFFFFu) : ~k;
    return __uint_as_float(b);
}

__device__ __forceinline__ u64 umax64(u64 a, u64 b) { return a > b ? a : b; }
__device__ __forceinline__ u64 umin64(u64 a, u64 b) { return a < b ? a : b; }

// =============================================================================
// Kernel A: key-map -> radix-select threshold -> compact -> hybrid bitonic ->
//           sigmoid+decode/clip (survivors only).  One block (1024 thr)/image.
//           (exact R16 state)
// =============================================================================
__global__ __launch_bounds__(1024)
void topk_decode_kernel(const float* __restrict__ obj_all,
                        const float* __restrict__ reg_all,
                        const float* __restrict__ anc_all)
{
    extern __shared__ unsigned char smem_raw[];
    u32* s_sb   = (u32*)smem_raw;                  // 30000 u32
    u64* s_keys = (u64*)(smem_raw + 120000);       // 2048 u64

    __shared__ u32 s_hist[256];
    __shared__ u32 s_cnt;
    __shared__ u32 s_prefix;
    __shared__ int s_K;

    const int img = blockIdx.x;
    const int tid = threadIdx.x;

    // ---- phase 1: monotonic key + transpose into smem ----
    {
        const float* obj = obj_all + (size_t)img * NANC;   // layout a*NHW + hw
        for (int i = tid; i < NANC; i += 1024) {
            int a  = i / NHW;
            int hw = i - a * NHW;
            s_sb[hw * NA + a] = fmap(obj[i]);
        }
    }
    if (tid == 0) { s_prefix = 0; s_K = PRE; }
    __syncthreads();

    // ---- phase 2: 4-pass MSB radix select for the PRE-th largest key ----
    u32 pmask = 0;
    for (int pass = 0; pass < 4; ++pass) {
        int shift = 24 - 8 * pass;
        if (tid < 256) s_hist[tid] = 0;
        __syncthreads();
        u32 prefix = s_prefix;
        for (int i = tid; i < NANC; i += 1024) {
            u32 v = s_sb[i];
            if ((v & pmask) == prefix)
                atomicAdd(&s_hist[(v >> shift) & 255u], 1u);
        }
        __syncthreads();
        // warp 0: shfl-based suffix scan over 256 bins
        if (tid < 32) {
            const int lane = tid;
            u32 h[8];
            u32 chunk = 0;
            #pragma unroll
            for (int j = 0; j < 8; ++j) { h[j] = s_hist[lane * 8 + j]; chunk += h[j]; }
            u32 s_incl = chunk;
            #pragma unroll
            for (int off = 1; off < 32; off <<= 1) {
                u32 t = __shfl_down_sync(0xFFFFFFFFu, s_incl, off);
                if (lane + off < 32) s_incl += t;
            }
            const u32 s_excl = s_incl - chunk;
            const int Kc = s_K;
            u32 suf = s_excl;
            #pragma unroll
            for (int j = 7; j >= 0; --j) {
                u32 nxt = suf;
                suf += h[j];
                if ((int)suf >= Kc && (int)nxt < Kc) {
                    s_K = Kc - (int)nxt;
                    s_prefix = prefix | ((u32)(lane * 8 + j) << shift);
                }
            }
        }
        pmask |= (0xFFu << shift);
        __syncthreads();
    }
    const u32 T = s_prefix;   // exact bits of the PRE-th largest key

    // ---- phase 3: compact candidates >= T ----
    if (tid == 0) s_cnt = 0;
    __syncthreads();
    for (int i = tid; i < NANC; i += 1024) {
        u32 v = s_sb[i];
        if (v >= T) {
            u32 pos = atomicAdd(&s_cnt, 1u);
            if (pos < PREP)
                s_keys[pos] = ((u64)v << 32) | (u64)(~(u32)i);
        }
    }
    __syncthreads();
    u32 n = s_cnt; if (n > PREP) n = PREP;
    for (int i = tid; i < PREP; i += 1024)
        if (i >= (int)n) s_keys[i] = 0ULL;
    __syncthreads();

    // ---- phase 4: hybrid bitonic sort (descending) of 2048 keys ----
    {
        const int e0 = 2 * tid;
        u64 a = s_keys[e0];
        u64 b = s_keys[e0 + 1];
        for (int k = 2; k <= PREP; k <<= 1) {
            const bool up = ((e0 & k) == 0);
            for (int j = k >> 1; j > 0; j >>= 1) {
                if (j == 1) {
                    if ((a < b) == up) { u64 t = a; a = b; b = t; }
                } else if (j <= 32) {
                    const int lx = j >> 1;
                    u64 pa = __shfl_xor_sync(0xFFFFFFFFu, a, lx);
                    u64 pb = __shfl_xor_sync(0xFFFFFFFFu, b, lx);
                    const bool lower = ((e0 & j) == 0);
                    a = (lower == up) ? umax64(a, pa) : umin64(a, pa);
                    b = (lower == up) ? umax64(b, pb) : umin64(b, pb);
                } else {
                    s_keys[e0]     = a;
                    s_keys[e0 + 1] = b;
                    __syncthreads();
                    u64 pa = s_keys[e0 ^ j];
                    u64 pb = s_keys[(e0 + 1) ^ j];
                    const bool lower = ((e0 & j) == 0);
                    a = (lower == up) ? umax64(a, pa) : umin64(a, pa);
                    b = (lower == up) ? umax64(b, pb) : umin64(b, pb);
                    __syncthreads();
                }
            }
        }
        s_keys[e0]     = a;
        s_keys[e0 + 1] = b;
        __syncthreads();
    }

    // ---- phase 5: sigmoid (survivors only) + decode / clip / validity ----
    const float* reg = reg_all + (size_t)img * NA * 4 * NHW;
    const float4* anc = (const float4*)anc_all + (size_t)img * NANC;
    for (int j = tid; j < PRE; j += 1024) {
        u64 key = s_keys[j];
        u32 idx = ~(u32)(key & 0xFFFFFFFFull);
        float o = funmap((u32)(key >> 32));
        float score = 1.0f / (1.0f + expf(-o));

        int hw = idx / NA;
        int a  = idx - hw * NA;
        const float* rb = reg + (a * 4) * NHW + hw;
        float dx = rb[0];
        float dy = rb[NHW];
        float dw = rb[2 * NHW];
        float dh = rb[3 * NHW];
        dw = fminf(dw, BBOX_CLIP);
        dh = fminf(dh, BBOX_CLIP);

        float4 A4 = anc[idx];
        float w  = A4.z - A4.x + 1.0f;
        float h  = A4.w - A4.y + 1.0f;
        float cx = A4.x + 0.5f * w;
        float cy = A4.y + 0.5f * h;

        float pcx = dx * w + cx;
        float pcy = dy * h + cy;
        float pw  = expf(dw) * w;
        float ph  = expf(dh) * h;

        float x1 = pcx - 0.5f * pw;
        float y1 = pcy - 0.5f * ph;
        float x2 = pcx + 0.5f * pw - 1.0f;
        float y2 = pcy + 0.5f * ph - 1.0f;

        x1 = fminf(fmaxf(x1, 0.0f), IMGW - 1.0f);
        x2 = fminf(fmaxf(x2, 0.0f), IMGW - 1.0f);
        y1 = fminf(fmaxf(y1, 0.0f), IMGW - 1.0f);
        y2 = fminf(fmaxf(y2, 0.0f), IMGW - 1.0f);

        float ws = x2 - x1 + 1.0f;
        float hs = y2 - y1 + 1.0f;
        float xc = x1 + ws * 0.5f;
        float yc = y1 + hs * 0.5f;
        unsigned char v = (ws >= 0.0f) & (hs >= 0.0f) & (xc < IMGW) & (yc < IMGW);

        g_boxes[img][j]  = make_float4(x1, y1, x2, y2);
        g_scores[img][j] = score;
        g_valid[img][j]  = v;
    }
    for (int j = PRE + tid; j < PREP; j += 1024) g_valid[img][j] = 0;
}

// =============================================================================
// Kernel B: NMS suppression bitmask — optimized this round.
//   - s_area[64]: column areas computed once per block (not per pair)
//   - zero-box fill for c >= PRE (no uninit smem reads)
//   - off-diagonal tiles (colBlk > row>>6): fully unrolled, NO per-iter checks
//   - diagonal tiles: col>row folded into the bit predicate (branchless)
//   Bits for cols >= PRE may be garbage — harmless: those candidates are
//   seeded "removed" via ~valid in kernel C and their state is never read.
// =============================================================================
__global__ __launch_bounds__(256)
void nms_mask_kernel()
{
    const int img    = blockIdx.z;
    const int colBlk = blockIdx.x;
    const int row    = blockIdx.y * 256 + threadIdx.x;
    const int rowWrd = row >> 6;

    __shared__ float4 s_col[64];
    __shared__ float  s_area[64];
    const int colBase = colBlk * 64;
    if (threadIdx.x < 64) {
        int c = colBase + threadIdx.x;
        float4 cb = (c < PRE) ? g_boxes[img][c] : make_float4(0.f, 0.f, 0.f, 0.f);
        s_col[threadIdx.x]  = cb;
        s_area[threadIdx.x] = (cb.z - cb.x + 1.0f) * (cb.w - cb.y + 1.0f);
    }
    __syncthreads();

    if (row >= PRE) return;
    if (colBlk < rowWrd) {                 // tile entirely below diagonal
        g_mask[img][row][colBlk] = 0ULL;
        return;
    }

    const float4 rb = g_boxes[img][row];
    const float rArea = (rb.z - rb.x + 1.0f) * (rb.w - rb.y + 1.0f);
    u64 bits = 0ULL;

    if (colBlk == rowWrd) {
        // diagonal tile: strict upper triangle via predicate
        #pragma unroll 8
        for (int jj = 0; jj < 64; ++jj) {
            float4 cb = s_col[jj];
            float xx1 = fmaxf(rb.x, cb.x);
            float yy1 = fmaxf(rb.y, cb.y);
            float xx2 = fminf(rb.z, cb.z);
            float yy2 = fminf(rb.w, cb.w);
            float iw = fmaxf(xx2 - xx1 + 1.0f, 0.0f);
            float ih = fmaxf(yy2 - yy1 + 1.0f, 0.0f);
            float inter = iw * ih;
            float iou = inter / (rArea + s_area[jj] - inter);
            if ((iou > NMS_THR) & (colBase + jj > row))
                bits |= (1ULL << jj);
        }
    } else {
        // off-diagonal tile: every col > row, no checks at all
        #pragma unroll 8
        for (int jj = 0; jj < 64; ++jj) {
            float4 cb = s_col[jj];
            float xx1 = fmaxf(rb.x, cb.x);
            float yy1 = fmaxf(rb.y, cb.y);
            float xx2 = fminf(rb.z, cb.z);
            float yy2 = fminf(rb.w, cb.w);
            float iw = fmaxf(xx2 - xx1 + 1.0f, 0.0f);
            float ih = fmaxf(yy2 - yy1 + 1.0f, 0.0f);
            float inter = iw * ih;
            float iou = inter / (rArea + s_area[jj] - inter);
            if (iou > NMS_THR)
                bits |= (1ULL << jj);
        }
    }
    g_mask[img][row][colBlk] = bits;
}

// =============================================================================
// Kernel C: greedy scan via double-buffered SMEM tiles. 256 threads/image.
//   (exact R14/R16 state)
// Output layout: boxes[8*1000*4] | scores[8*1000] | valid[8*1000]  (float32)
// =============================================================================
__global__ __launch_bounds__(256)
void nms_reduce_kernel(float* __restrict__ out)
{
    const int img  = blockIdx.x;
    const int tid  = threadIdx.x;
    const int lane = tid & 31;
    const int wid  = tid >> 5;

    __shared__ u64 s_tile[2][64][NWRD];      // 32 KB double-buffered mask tile
    __shared__ int s_kept[POST];
    __shared__ int s_kdone;

    float* outB = out;                       // (8,1000,4)
    float* outS = out + NIMG * POST * 4;     // (8,1000)
    float* outV = out + NIMG * POST * 5;     // (8,1000)

    for (int i = tid; i < POST * 4; i += 256) outB[img * POST * 4 + i] = 0.0f;
    for (int i = tid; i < POST;     i += 256) {
        outS[img * POST + i] = 0.0f;
        outV[img * POST + i] = 0.0f;
    }
    if (tid == 0) s_kdone = 0;

    // preload tile 0 (all threads)
    {
        const u64* src = &g_mask[img][0][0];
        for (int i = tid; i < 64 * NWRD; i += 256)
            s_tile[0][0][i] = src[i];
    }

    // scanner warp state: removed-word per lane, seeded by ~valid
    u64 rw = 0ULL;
    if (wid == 0) {
        const u64* vp = (const u64*)g_valid[img];
        u64 bits = 0ULL;
        #pragma unroll
        for (int q = 0; q < 8; ++q) {
            u64 v8 = vp[lane * 8 + q];
            #pragma unroll
            for (int b = 0; b < 8; ++b)
                if ((v8 >> (8 * b)) & 0xFFull) bits |= 1ULL << (q * 8 + b);
        }
        rw = ~bits;
    }
    __syncthreads();

    int k = 0;
    for (int t = 0; t < NTILE; ++t) {
        if (wid >= 1) {
            const int t1 = t + 1;
            if (t1 < NTILE) {
                const int r0 = t1 * 64;
                const int nval = (PRE - r0 < 64 ? PRE - r0 : 64) * NWRD;
                const u64* src = &g_mask[img][r0][0];
                u64* dst = &s_tile[t1 & 1][0][0];
                for (int i = tid - 32; i < 64 * NWRD; i += 224)
                    dst[i] = (i < nval) ? src[i] : 0ULL;
            }
        } else {
            const u64 (*tp)[NWRD] = s_tile[t & 1];
            u64 cur = __shfl_sync(0xFFFFFFFFu, rw, t);
            u64 keptw = 0ULL;
            #pragma unroll 1
            for (int g = 0; g < 8; ++g) {
                const int j0 = g * 8;
                u64 m[8], ms[8];
                #pragma unroll
                for (int j = 0; j < 8; ++j) {
                    m[j]  = tp[j0 + j][lane];
                    ms[j] = tp[j0 + j][t];
                }
                #pragma unroll
                for (int j = 0; j < 8; ++j) {
                    const u64 bitj = 1ULL << (j0 + j);
                    const bool kept = (cur & bitj) == 0ULL;
                    cur   |= kept ? ms[j] : 0ULL;
                    rw    |= kept ? m[j]  : 0ULL;
                    keptw |= kept ? bitj  : 0ULL;
                }
            }
            const u32 lo = (u32)keptw, hi = (u32)(keptw >> 32);
            const int nlo = __popc(lo);
            const int ncnt = nlo + __popc(hi);
            #pragma unroll
            for (int r = 0; r < 2; ++r) {
                const int idx = lane + r * 32;
                if (idx < ncnt && k + idx < POST) {
                    int pos = (idx < nlo) ? __fns(lo, 0, idx + 1)
                                          : 32 + __fns(hi, 0, idx - nlo + 1);
                    s_kept[k + idx] = t * 64 + pos;
                }
            }
            k += ncnt;
            if (lane == 0) s_kdone = k;
        }
        __syncthreads();
        if (s_kdone >= POST) break;
    }

    const int nk = (s_kdone < POST) ? s_kdone : POST;
    for (int j = tid; j < nk; j += 256) {
        int i = s_kept[j];
        float4 b = g_boxes[img][i];
        ((float4*)outB)[img * POST + j] = b;
        outS[img * POST + j] = g_scores[img][i];
        outV[img * POST + j] = 1.0f;
    }
}

// =============================================================================
extern "C" void kernel_launch(void* const* d_in, const int* in_sizes, int n_in,
                              void* d_out, int out_size)
{
    const float* obj = (const float*)d_in[0];   // (8,3,100,100)
    const float* reg = (const float*)d_in[1];   // (8,12,100,100)
    const float* anc = (const float*)d_in[2];   // (8,30000,4)
    float* out = (float*)d_out;
    (void)in_sizes; (void)n_in; (void)out_size;

    const int smemA = 120000 + PREP * 8;        // 136384 bytes dynamic
    cudaFuncSetAttribute(topk_decode_kernel,
                         cudaFuncAttributeMaxDynamicSharedMemorySize, smemA);

    topk_decode_kernel<<<NIMG, 1024, smemA>>>(obj, reg, anc);
    dim3 gB(NWRD, 8, NIMG);
    nms_mask_kernel<<<gB, 256>>>();
    nms_reduce_kernel<<<NIMG, 256>>>(out);
}